// round 5
// baseline (speedup 1.0000x reference)
#include <cuda_runtime.h>
#include <math_constants.h>

// Problem constants (B=8, S=1024, V=32000)
#define BB 8
#define SS 1024
#define VV 32000
#define V4 (VV / 4)            // 8000 float4 per logits row
#define NVERIFY BB             // 8 verify blocks (one per batch row)
#define NCOPY 64               // 64 speculative-copy blocks
#define F4_PER_COPY (BB * V4 / NCOPY)   // 1000 float4 per copy block
#define NBLK (NVERIFY + NCOPY)

// Device scratch (zero-init at load; self-reset by last block out each run).
__device__ int g_copy_fin;     // # copy blocks done (rare-path wait target)
__device__ int g_fin;          // last-block-out reset counter

// Output layout (float32, tuple order):
//   [0 .. B*S)               draft        (8192)
//   [B*S .. B*S+B)           num_newly    (8)
//   [B*S+B .. B*S+2B)        num_acc      (8)
//   [B*S+2B .. +B*V)         last_logits  (256000)
#define OFF_NEWLY   (BB * SS)
#define OFF_ACC     (BB * SS + BB)
#define OFF_LOGITS  (BB * SS + 2 * BB)

__device__ __forceinline__ int ld_acquire(const int* p) {
    int v;
    asm volatile("ld.acquire.gpu.b32 %0, [%1];" : "=r"(v) : "l"(p) : "memory");
    return v;
}

__global__ __launch_bounds__(1024) void eagle_kernel(
    const int*   __restrict__ input_ids,   // [B, S]
    const float* __restrict__ logits,      // [B, S, V]
    const int*   __restrict__ npa,         // [B]
    float*       __restrict__ out)
{
    const int tid = threadIdx.x;

    if (blockIdx.x >= NVERIFY) {
        // ============ SPECULATIVE COPY (common case: num_newly == 0) ========
        // last_logits[b] = logits[b, npa[b]-1, :], issued with no waiting.
        const int g    = blockIdx.x - NVERIFY;        // 0..63
        const int b    = g / (NCOPY / BB);            // 8 copy blocks per row
        const int base = (g % (NCOPY / BB)) * F4_PER_COPY;

        const int start = npa[b] - 1;                 // broadcast load
        const float4* src = (const float4*)(logits +
                              ((size_t)b * SS + (size_t)start) * VV) + base;
        float4* dst = (float4*)(out + OFF_LOGITS) + (size_t)b * V4 + base;

        if (tid < F4_PER_COPY) dst[tid] = src[tid];

        // Publish completion for the (rare) correction path.
        __syncthreads();
        if (tid == 0) {
            __threadfence();
            atomicAdd(&g_copy_fin, 1);
        }
    } else {
        // ================= VERIFY (one block per batch row) =================
        const int b    = blockIdx.x;
        const int lane = tid & 31;
        const int warp = tid >> 5;

        __shared__ float s_val[32];
        __shared__ int   s_idx[32];
        __shared__ int   s_cont;
        __shared__ int   s_bonus;

        const int* ids = input_ids + b * SS;

        // Prefetch draft source ids (coalesced 4KB) — overlaps npa latency.
        int myid = (tid < SS - 1) ? ids[tid + 1] : 0;

        const int start = npa[b] - 1;
        int k = start;

        const bool tail = (tid + 7 * 1024) < V4;   // threads >= 832 skip j=7

        for (;;) {
            const float4* row =
                (const float4*)(logits + ((size_t)b * SS + (size_t)k) * VV);
            const int expect = (k < SS - 1) ? ids[k + 1] : -1;

            // ---- front-batched row load (MLP=8) + per-thread argmax ----
            float4 v[8];
            #pragma unroll
            for (int j = 0; j < 7; j++) v[j] = row[tid + j * 1024];
            if (tail) v[7] = row[tid + 7 * 1024];

            float best = -CUDART_INF_F;
            int   bidx = 0x7fffffff;
            #pragma unroll
            for (int j = 0; j < 8; j++) {
                if (j < 7 || tail) {
                    const int base = (tid + j * 1024) * 4;
                    const float4 w = v[j];
                    // increasing index + strict '>' => first-occurrence max
                    if (w.x > best) { best = w.x; bidx = base;     }
                    if (w.y > best) { best = w.y; bidx = base + 1; }
                    if (w.z > best) { best = w.z; bidx = base + 2; }
                    if (w.w > best) { best = w.w; bidx = base + 3; }
                }
            }
            #pragma unroll
            for (int off = 16; off > 0; off >>= 1) {
                float ov = __shfl_down_sync(0xffffffffu, best, off);
                int   oi = __shfl_down_sync(0xffffffffu, bidx, off);
                if (ov > best || (ov == best && oi < bidx)) { best = ov; bidx = oi; }
            }
            if (lane == 0) { s_val[warp] = best; s_idx[warp] = bidx; }
            __syncthreads();

            if (warp == 0) {
                float v0 = s_val[lane];
                int   i0 = s_idx[lane];
                #pragma unroll
                for (int off = 16; off > 0; off >>= 1) {
                    float ov = __shfl_down_sync(0xffffffffu, v0, off);
                    int   oi = __shfl_down_sync(0xffffffffu, i0, off);
                    if (ov > v0 || (ov == v0 && oi < i0)) { v0 = ov; i0 = oi; }
                }
                if (lane == 0) {
                    if (k < SS - 1 && i0 == expect) {
                        s_cont = 1;
                    } else {
                        s_cont  = 0;
                        s_bonus = i0;
                        out[OFF_NEWLY + b] = (float)(k - start);   // num_newly
                        out[OFF_ACC   + b] = (float)(k + 1);       // num_acc
                    }
                }
            }
            __syncthreads();
            if (!s_cont) break;
            ++k;
        }

        // ---- draft row (one element per thread; S == blockDim) ----
        int dv;
        if (tid < k)        dv = myid;
        else if (tid == k)  dv = s_bonus;
        else                dv = 0;
        out[b * SS + tid] = (float)dv;

        // ---- RARE correction path: speculation wrong (num_newly > 0) ----
        if (k != start) {
            // Wait until every copy block has finished its speculative store,
            // then overwrite this row's last_logits with the correct row.
            if (tid == 0)
                while (ld_acquire(&g_copy_fin) < NCOPY) __nanosleep(100);
            __syncthreads();

            const float4* row =
                (const float4*)(logits + ((size_t)b * SS + (size_t)k) * VV);
            float4* dst = (float4*)(out + OFF_LOGITS) + (size_t)b * V4;
            for (int i = tid; i < V4; i += 1024) dst[i] = row[i];
        }
    }

    // ---- self-cleaning reset: last block out zeroes the counters ----
    __syncthreads();
    if (tid == 0) {
        int prev = atomicAdd(&g_fin, 1);
        if (prev == NBLK - 1) {
            g_fin = 0;
            g_copy_fin = 0;
        }
    }
}

extern "C" void kernel_launch(void* const* d_in, const int* in_sizes, int n_in,
                              void* d_out, int out_size) {
    const int*   input_ids = (const int*)  d_in[0];
    const float* logits    = (const float*)d_in[1];
    const int*   npa       = (const int*)  d_in[2];
    float* out = (float*)d_out;

    eagle_kernel<<<NBLK, 1024>>>(input_ids, logits, npa, out);
}

// round 7
// speedup vs baseline: 1.2952x; 1.2952x over previous
#include <cuda_runtime.h>
#include <math_constants.h>
#include <cstdint>

// Problem constants (B=8, S=1024, V=32000)
#define BB 8
#define SS 1024
#define VV 32000
#define V4 (VV / 4)          // 8000 float4 per logits row
#define NSPLIT 4             // CTAs per batch row (one cluster)
#define QF4 (V4 / NSPLIT)    // 2000 float4 per quarter
#define NBLK (BB * NSPLIT)   // 32 CTAs total

// Output layout (float32, tuple order):
//   [0 .. B*S)               draft        (8192)
//   [B*S .. B*S+B)           num_newly    (8)
//   [B*S+B .. B*S+2B)        num_acc      (8)
//   [B*S+2B .. +B*V)         last_logits  (256000)
#define OFF_NEWLY   (BB * SS)
#define OFF_ACC     (BB * SS + BB)
#define OFF_LOGITS  (BB * SS + 2 * BB)

__device__ __forceinline__ uint32_t smem_u32(const void* p) {
    uint32_t a;
    asm("{ .reg .u64 t; cvta.to.shared.u64 t, %1; cvt.u32.u64 %0, t; }"
        : "=r"(a) : "l"(p));
    return a;
}

// Monotone packing: larger float first, then smaller index on ties.
__device__ __forceinline__ unsigned long long pack_cand(float v, int idx) {
    unsigned u   = __float_as_uint(v);
    unsigned ord = (u & 0x80000000u) ? ~u : (u | 0x80000000u);
    return ((unsigned long long)ord << 32) | (unsigned)(~idx);
}

__global__ __launch_bounds__(1024) __cluster_dims__(NSPLIT, 1, 1)
void eagle_kernel(
    const int*   __restrict__ input_ids,   // [B, S]
    const float* __restrict__ logits,      // [B, S, V]
    const int*   __restrict__ npa,         // [B]
    float*       __restrict__ out)
{
    const int b    = blockIdx.x >> 2;    // batch row (cluster id)
    const int tid  = threadIdx.x;
    const int lane = tid & 31;
    const int warp = tid >> 5;

    uint32_t rank;                        // CTA rank within cluster = quarter
    asm("mov.u32 %0, %%cluster_ctarank;" : "=r"(rank));
    const int q = (int)rank;

    __shared__ float s_val[32];
    __shared__ int   s_idx[32];
    __shared__ unsigned long long m_cand[NSPLIT];  // rank0's merge mailbox
    __shared__ int   s_i0, s_cont, s_bonus;

    const int* ids   = input_ids + b * SS;
    const int  start = npa[b] - 1;

    // rank0 prefetches draft source ids (it alone writes the draft row)
    int myid = 0;
    if (q == 0 && tid < SS - 1) myid = ids[tid + 1];

    // ---- load this CTA's 32KB quarter of row `start` ----
    const float4* rowq =
        (const float4*)(logits + ((size_t)b * SS + (size_t)start) * VV) + q * QF4;
    const bool t2 = (tid + 1024) < QF4;          // QF4=2000: threads < 976
    float4 v0 = rowq[tid];
    float4 v1 = t2 ? rowq[tid + 1024] : make_float4(0.f, 0.f, 0.f, 0.f);

    // ---- speculative store: common case this IS last_logits[b] ----
    float4* dstq = (float4*)(out + OFF_LOGITS) + (size_t)b * V4 + q * QF4;
    dstq[tid] = v0;
    if (t2) dstq[tid + 1024] = v1;

    // ---- per-thread partial argmax (global indices, first-occurrence) ----
    float best = -CUDART_INF_F;
    int   bidx = 0x7fffffff;
    {
        int base = (q * QF4 + tid) * 4;
        if (v0.x > best) { best = v0.x; bidx = base;     }
        if (v0.y > best) { best = v0.y; bidx = base + 1; }
        if (v0.z > best) { best = v0.z; bidx = base + 2; }
        if (v0.w > best) { best = v0.w; bidx = base + 3; }
        if (t2) {
            base = (q * QF4 + tid + 1024) * 4;
            if (v1.x > best) { best = v1.x; bidx = base;     }
            if (v1.y > best) { best = v1.y; bidx = base + 1; }
            if (v1.z > best) { best = v1.z; bidx = base + 2; }
            if (v1.w > best) { best = v1.w; bidx = base + 3; }
        }
    }
    #pragma unroll
    for (int off = 16; off > 0; off >>= 1) {
        float ov = __shfl_down_sync(0xffffffffu, best, off);
        int   oi = __shfl_down_sync(0xffffffffu, bidx, off);
        if (ov > best || (ov == best && oi < bidx)) { best = ov; bidx = oi; }
    }
    if (lane == 0) { s_val[warp] = best; s_idx[warp] = bidx; }
    __syncthreads();

    if (warp == 0) {
        float v = s_val[lane];
        int   i = s_idx[lane];
        #pragma unroll
        for (int off = 16; off > 0; off >>= 1) {
            float ov = __shfl_down_sync(0xffffffffu, v, off);
            int   oi = __shfl_down_sync(0xffffffffu, i, off);
            if (ov > v || (ov == v && oi < i)) { v = ov; i = oi; }
        }
        if (lane == 0) {
            unsigned long long pk = pack_cand(v, i);
            // Deposit candidate into rank 0's mailbox slot [q] via DSMEM.
            uint32_t laddr = smem_u32(&m_cand[q]);
            asm volatile(
                "{ .reg .b32 r;\n\t"
                "  mapa.shared::cluster.u32 r, %0, %1;\n\t"
                "  st.shared::cluster.b64 [r], %2; }"
                :: "r"(laddr), "r"(0), "l"(pk) : "memory");
        }
    }

    // Cluster barrier (acq_rel): publishes mailbox writes AND orders all
    // speculative global stores before rank0's post-barrier work.
    asm volatile("barrier.cluster.arrive.aligned;" ::: "memory");
    asm volatile("barrier.cluster.wait.aligned;"   ::: "memory");

    if (q != 0) return;   // non-leader CTAs are done

    // ===================== RANK-0 FINISHER =====================
    if (tid == 0) {
        unsigned long long pk = m_cand[0];
        #pragma unroll
        for (int j = 1; j < NSPLIT; j++)
            if (m_cand[j] > pk) pk = m_cand[j];
        s_i0 = (int)(~(unsigned)(pk & 0xFFFFFFFFull));
    }
    __syncthreads();

    int i0 = s_i0;
    int k  = start;

    for (;;) {
        if (tid == 0) {
            if (k < SS - 1 && i0 == ids[k + 1]) {
                s_cont = 1;
            } else {
                s_cont  = 0;
                s_bonus = i0;
                out[OFF_NEWLY + b] = (float)(k - start);   // num_newly
                out[OFF_ACC   + b] = (float)(k + 1);       // num_acc
            }
        }
        __syncthreads();
        if (!s_cont) break;
        ++k;

        // ---- RARE path: full-row argmax of row k by this CTA alone ----
        const float4* row =
            (const float4*)(logits + ((size_t)b * SS + (size_t)k) * VV);
        float bb2 = -CUDART_INF_F;
        int   bi2 = 0x7fffffff;
        for (int i2 = tid; i2 < V4; i2 += 1024) {
            float4 w = row[i2];
            int base = i2 * 4;
            if (w.x > bb2) { bb2 = w.x; bi2 = base;     }
            if (w.y > bb2) { bb2 = w.y; bi2 = base + 1; }
            if (w.z > bb2) { bb2 = w.z; bi2 = base + 2; }
            if (w.w > bb2) { bb2 = w.w; bi2 = base + 3; }
        }
        #pragma unroll
        for (int off = 16; off > 0; off >>= 1) {
            float ov = __shfl_down_sync(0xffffffffu, bb2, off);
            int   oi = __shfl_down_sync(0xffffffffu, bi2, off);
            if (ov > bb2 || (ov == bb2 && oi < bi2)) { bb2 = ov; bi2 = oi; }
        }
        if (lane == 0) { s_val[warp] = bb2; s_idx[warp] = bi2; }
        __syncthreads();
        if (warp == 0) {
            float v = s_val[lane];
            int   i = s_idx[lane];
            #pragma unroll
            for (int off = 16; off > 0; off >>= 1) {
                float ov = __shfl_down_sync(0xffffffffu, v, off);
                int   oi = __shfl_down_sync(0xffffffffu, i, off);
                if (ov > v || (ov == v && oi < i)) { v = ov; i = oi; }
            }
            if (lane == 0) s_i0 = i;
        }
        __syncthreads();
        i0 = s_i0;
    }

    // ---- draft row (one element per thread; S == blockDim) ----
    int dv;
    if (tid < k)        dv = myid;
    else if (tid == k)  dv = s_bonus;
    else                dv = 0;
    out[b * SS + tid] = (float)dv;

    // ---- RARE correction: overwrite speculative last_logits with row k ----
    // Ordering vs. all CTAs' speculative stores was established by the
    // cluster barrier above.
    if (k != start) {
        const float4* row =
            (const float4*)(logits + ((size_t)b * SS + (size_t)k) * VV);
        float4* d2 = (float4*)(out + OFF_LOGITS) + (size_t)b * V4;
        for (int i2 = tid; i2 < V4; i2 += 1024) d2[i2] = row[i2];
    }
}

extern "C" void kernel_launch(void* const* d_in, const int* in_sizes, int n_in,
                              void* d_out, int out_size) {
    const int*   input_ids = (const int*)  d_in[0];
    const float* logits    = (const float*)d_in[1];
    const int*   npa       = (const int*)  d_in[2];
    float* out = (float*)d_out;

    eagle_kernel<<<NBLK, 1024>>>(input_ids, logits, npa, out);
}